// round 12
// baseline (speedup 1.0000x reference)
#include <cuda_runtime.h>
#include <cuda_bf16.h>
#include <cstdint>

// ---------------------------------------------------------------------------
// GIN via mma.sync.m16n8k16.bf16 double-bf16 split (3-product ~fp32):
//   a = a0 + a1 (bf16 each);  D += a0b0 + a0b1 + a1b0  (err ~2^-17/product)
// GEMM: cp.async.cg double-buffered staging, 2 CTAs/SM, 8 warps (2m x 4n),
// warp tile 64x32, BK=32. A fragments loaded via ldmatrix.x4 (4x fewer LDS).
// Operands pre-split & pair-packed (u32 = bf16[k],bf16[k+1]).
// ---------------------------------------------------------------------------

#define MAXN 50000
#define MAXE 1000000

__device__ __align__(16) unsigned g_P0[MAXN * 128];
__device__ __align__(16) unsigned g_P1[MAXN * 128];
__device__ __align__(16) unsigned g_Q0[MAXN * 128];
__device__ __align__(16) unsigned g_Q1[MAXN * 128];
__device__ __align__(16) float    g_hf[MAXN * 128];   // fp32 h1 (gather2 input)
__device__ __align__(16) unsigned g_W0[128 * 256];    // split weights [K/2][NW]
__device__ __align__(16) unsigned g_W1[128 * 256];
__device__ int g_rowptr[MAXN + 1];
__device__ int g_cursor[MAXN];
__device__ int g_deg   [MAXN];
__device__ int g_srcs  [MAXE];
__device__ int g_src32 [MAXE];
__device__ int g_dst32 [MAXE];
__device__ int g_bsum  [256];
__device__ int g_is64;

__device__ __forceinline__ const unsigned* planeR(int sel, int p) {
    if (sel == 0) return p ? g_P1 : g_P0;
    return p ? g_Q1 : g_Q0;
}
__device__ __forceinline__ unsigned* planeW(int sel, int p) {
    if (sel == 0) return p ? g_P1 : g_P0;
    return p ? g_Q1 : g_Q0;
}

__device__ __forceinline__ void split2(float e, float o,
                                       unsigned& hi, unsigned& lo) {
    __nv_bfloat16 he = __float2bfloat16_rn(e);
    __nv_bfloat16 ho = __float2bfloat16_rn(o);
    float re = e - __bfloat162float(he);
    float ro = o - __bfloat162float(ho);
    __nv_bfloat16 rhe = __float2bfloat16_rn(re);
    __nv_bfloat16 rho = __float2bfloat16_rn(ro);
    hi = ((unsigned)__bfloat16_as_ushort(ho) << 16) | __bfloat16_as_ushort(he);
    lo = ((unsigned)__bfloat16_as_ushort(rho) << 16) | __bfloat16_as_ushort(rhe);
}

#define MMA_BF16(d, a, b)                                                     \
    asm volatile(                                                             \
        "mma.sync.aligned.m16n8k16.row.col.f32.bf16.bf16.f32 "               \
        "{%0,%1,%2,%3},{%4,%5,%6,%7},{%8,%9},{%0,%1,%2,%3};"                 \
        : "+f"((d)[0]), "+f"((d)[1]), "+f"((d)[2]), "+f"((d)[3])             \
        : "r"((a)[0]), "r"((a)[1]), "r"((a)[2]), "r"((a)[3]),                \
          "r"((b)[0]), "r"((b)[1]))

#define LDMX4(r, addr)                                                        \
    asm volatile(                                                             \
        "ldmatrix.sync.aligned.m8n8.x4.shared.b16 {%0,%1,%2,%3}, [%4];"      \
        : "=r"((r)[0]), "=r"((r)[1]), "=r"((r)[2]), "=r"((r)[3])             \
        : "r"(addr))

// 16B cp.async with zero-fill when pred is false (src-size=0 form)
__device__ __forceinline__ void cp16(uint32_t dst, const void* src, bool pred) {
    int sz = pred ? 16 : 0;
    asm volatile("cp.async.cg.shared.global [%0], [%1], 16, %2;"
                 :: "r"(dst), "l"(src), "r"(sz) : "memory");
}
#define CP_COMMIT() asm volatile("cp.async.commit_group;" ::: "memory")
#define CP_WAIT(n)  asm volatile("cp.async.wait_group %0;" :: "n"(n) : "memory")

// ======================= edge-index dtype handling ==========================
__global__ void detect_idx64(const unsigned int* __restrict__ w) {
    if (threadIdx.x == 0 && blockIdx.x == 0) {
        unsigned int o = 0;
        #pragma unroll 1
        for (int i = 1; i < 256; i += 2) o |= w[i];
        g_is64 = (o == 0) ? 1 : 0;
    }
}
__global__ void convert_idx(const unsigned int* __restrict__ w, int E, int N) {
    const int e = blockIdx.x * blockDim.x + threadIdx.x;
    if (e >= E) return;
    int s, d;
    if (g_is64) { s = (int)w[2 * e]; d = (int)w[2 * (E + e)]; }
    else        { s = (int)w[e];     d = (int)w[E + e]; }
    s = min(max(s, 0), N - 1);
    d = min(max(d, 0), N - 1);
    g_src32[e] = s;
    g_dst32[e] = d;
}

// ============================ CSR construction ==============================
__global__ void zero_deg(int N) {
    int i = blockIdx.x * blockDim.x + threadIdx.x;
    if (i < N) g_deg[i] = 0;
}
__global__ void hist_deg(int E) {
    int e = blockIdx.x * blockDim.x + threadIdx.x;
    if (e < E) atomicAdd(&g_deg[g_dst32[e]], 1);
}
__global__ void scan_block(int N) {
    __shared__ int s[256];
    const int t = threadIdx.x;
    const int i = blockIdx.x * 256 + t;
    const int v = (i < N) ? g_deg[i] : 0;
    s[t] = v;
    __syncthreads();
    #pragma unroll
    for (int off = 1; off < 256; off <<= 1) {
        int tmp = (t >= off) ? s[t - off] : 0;
        __syncthreads();
        s[t] += tmp;
        __syncthreads();
    }
    if (i < N) g_rowptr[i] = s[t] - v;
    if (t == 255) g_bsum[blockIdx.x] = s[255];
}
__global__ void scan_partials(int B) {
    __shared__ int s[256];
    const int t = threadIdx.x;
    const int v = (t < B) ? g_bsum[t] : 0;
    s[t] = v;
    __syncthreads();
    #pragma unroll
    for (int off = 1; off < 256; off <<= 1) {
        int tmp = (t >= off) ? s[t - off] : 0;
        __syncthreads();
        s[t] += tmp;
        __syncthreads();
    }
    if (t < B) g_bsum[t] = s[t] - v;
}
__global__ void scan_add(int N, int E) {
    int i = blockIdx.x * blockDim.x + threadIdx.x;
    if (i < N) {
        int r = g_rowptr[i] + g_bsum[blockIdx.x];
        g_rowptr[i] = r;
        g_cursor[i] = r;
    }
    if (i == N) g_rowptr[N] = E;
}
__global__ void fill_csr(int E) {
    int e = blockIdx.x * blockDim.x + threadIdx.x;
    if (e >= E) return;
    int p = atomicAdd(&g_cursor[g_dst32[e]], 1);
    g_srcs[p] = g_src32[e];
}

// ===================== GIN aggregation (split output) =======================
__global__ void gin_aggregate_split(const float* __restrict__ h_ext,
                                    int use_ext, int N) {
    const int warp = (blockIdx.x * blockDim.x + threadIdx.x) >> 5;
    if (warp >= N) return;
    const int lane = threadIdx.x & 31;
    const float* __restrict__ h = use_ext ? h_ext : g_hf;
    const float4* __restrict__ hp = reinterpret_cast<const float4*>(h);
    float4 acc = hp[(size_t)warp * 32 + lane];
    const int beg = g_rowptr[warp];
    const int end = g_rowptr[warp + 1];
    for (int j = beg; j < end; j++) {
        const int s = g_srcs[j];
        const float4 v = hp[(size_t)s * 32 + lane];
        acc.x += v.x; acc.y += v.y; acc.z += v.z; acc.w += v.w;
    }
    unsigned h0, l0, h1, l1;
    split2(acc.x, acc.y, h0, l0);
    split2(acc.z, acc.w, h1, l1);
    const size_t o = (size_t)warp * 32 + lane;
    reinterpret_cast<uint2*>(g_P0)[o] = make_uint2(h0, h1);
    reinterpret_cast<uint2*>(g_P1)[o] = make_uint2(l0, l1);
}

// ===================== weight split/pack: W[K][N] -> [K/2][NW] ==============
__global__ void prep_w(const float* __restrict__ W, int K, int N_real, int NW) {
    int idx = blockIdx.x * blockDim.x + threadIdx.x;
    if (idx >= (K >> 1) * NW) return;
    int kp = idx / NW, n = idx % NW;
    float e = 0.f, o = 0.f;
    if (n < N_real) {
        e = W[(size_t)(2 * kp) * N_real + n];
        o = W[(size_t)(2 * kp + 1) * N_real + n];
    }
    unsigned hi, lo;
    split2(e, o, hi, lo);
    g_W0[idx] = hi;
    g_W1[idx] = lo;
}

// ======================= bf16x3 GEMM (mma.m16n8k16) =========================
// cp.async double-buffered. Per stage (u32): As0[128][20] As1 Bs0[16][136] Bs1
// Stage stride = 2*2560 + 2*2176 = 9472 u32. Two stages = 75776 B.
// A fragments via ldmatrix.x4: matrices {r0..r0+7, r0+8..r0+15} x {k0, k1}.
// CMODE: 0 = split planes (c_sel), 1 = fp32 g_hf, 2 = external fp32 (masked).
template<bool RELU, int CMODE>
__global__ void __launch_bounds__(256, 2)
gemm_bf16(int a_sel, int c_sel, float* __restrict__ c_ext,
          const float* __restrict__ bias, int M, int N_real, int NW, int K)
{
    extern __shared__ __align__(16) unsigned smem[];
    constexpr int STG = 9472;            // u32 per stage
    const uint32_t smem_b = (uint32_t)__cvta_generic_to_shared(smem);

    const int tid  = threadIdx.x;
    const int wid  = tid >> 5;
    const int lane = tid & 31;
    const int gid  = lane >> 2;
    const int tig  = lane & 3;
    const int wm   = wid >> 2;
    const int wn   = wid & 3;
    const int row0 = blockIdx.y * 128;
    const int col0 = blockIdx.x * 128;

    const unsigned* __restrict__ A0g = planeR(a_sel, 0);
    const unsigned* __restrict__ A1g = planeR(a_sel, 1);

    const int a_r = tid >> 1, a_seg = (tid & 1) * 8;
    const int b_kp = tid >> 4, b_c0 = (tid & 15) * 8;
    const int a_gr = row0 + a_r;
    const bool a_ok = (a_gr < M);
    const int Kh = K >> 1;

    // ldmatrix per-lane byte offset: row = (lane&15), k-col group = lane>>4
    const uint32_t ldm_lane = (uint32_t)(((lane & 15) * 20 + (lane >> 4) * 4) * 4);

    float acc[4][4][4];
    #pragma unroll
    for (int mt = 0; mt < 4; mt++)
        #pragma unroll
        for (int nt = 0; nt < 4; nt++)
            #pragma unroll
            for (int q = 0; q < 4; q++) acc[mt][nt][q] = 0.f;

    auto stage = [&](int ch, int buf) {
        const int kp0 = ch << 4;
        const uint32_t sb = smem_b + (uint32_t)(buf * STG) * 4u;
        const uint32_t a_off = (uint32_t)(a_r * 20 + a_seg) * 4u;
        cp16(sb + a_off,      A0g + (size_t)a_gr * Kh + kp0 + a_seg,     a_ok);
        cp16(sb + a_off + 16, A0g + (size_t)a_gr * Kh + kp0 + a_seg + 4, a_ok);
        cp16(sb + 2560u * 4u + a_off,      A1g + (size_t)a_gr * Kh + kp0 + a_seg,     a_ok);
        cp16(sb + 2560u * 4u + a_off + 16, A1g + (size_t)a_gr * Kh + kp0 + a_seg + 4, a_ok);
        const uint32_t b_off = (uint32_t)(b_kp * 136 + b_c0) * 4u;
        const size_t bg = (size_t)(kp0 + b_kp) * NW + col0 + b_c0;
        cp16(sb + 5120u * 4u + b_off,      g_W0 + bg,     true);
        cp16(sb + 5120u * 4u + b_off + 16, g_W0 + bg + 4, true);
        cp16(sb + 7296u * 4u + b_off,      g_W1 + bg,     true);
        cp16(sb + 7296u * 4u + b_off + 16, g_W1 + bg + 4, true);
        CP_COMMIT();
    };

    const int nch = K >> 5;
    stage(0, 0);
    for (int ch = 0; ch < nch; ch++) {
        if (ch + 1 < nch) {
            stage(ch + 1, (ch + 1) & 1);
            CP_WAIT(1);
        } else {
            CP_WAIT(0);
        }
        __syncthreads();

        const uint32_t Sb  = smem_b + (uint32_t)((ch & 1) * STG) * 4u;
        const unsigned* S   = smem + (ch & 1) * STG;
        const unsigned* Bs0 = S + 5120;
        const unsigned* Bs1 = S + 7296;

        #pragma unroll
        for (int s = 0; s < 2; s++) {
            const int so = s * 8;
            uint32_t B0f[4][2], B1f[4][2];
            #pragma unroll
            for (int nt = 0; nt < 4; nt++) {
                const int c = wn * 32 + nt * 8 + gid;
                B0f[nt][0] = Bs0[(so + tig    ) * 136 + c];
                B0f[nt][1] = Bs0[(so + tig + 4) * 136 + c];
                B1f[nt][0] = Bs1[(so + tig    ) * 136 + c];
                B1f[nt][1] = Bs1[(so + tig + 4) * 136 + c];
            }
            #pragma unroll
            for (int mt = 0; mt < 4; mt++) {
                const uint32_t r0off = (uint32_t)(((wm * 64 + mt * 16) * 20 + so) * 4);
                uint32_t A0f[4], A1f[4];
                LDMX4(A0f, Sb + r0off + ldm_lane);                   // plane 0
                LDMX4(A1f, Sb + 2560u * 4u + r0off + ldm_lane);      // plane 1
                #pragma unroll
                for (int nt = 0; nt < 4; nt++)
                    MMA_BF16(acc[mt][nt], A0f, B0f[nt]);   // a0*b0
                #pragma unroll
                for (int nt = 0; nt < 4; nt++)
                    MMA_BF16(acc[mt][nt], A0f, B1f[nt]);   // a0*b1
                #pragma unroll
                for (int nt = 0; nt < 4; nt++)
                    MMA_BF16(acc[mt][nt], A1f, B0f[nt]);   // a1*b0
            }
        }
        __syncthreads();
    }

    // ---- epilogue ----
    unsigned* C0 = planeW(c_sel, 0);
    unsigned* C1 = planeW(c_sel, 1);
    #pragma unroll
    for (int mt = 0; mt < 4; mt++) {
        #pragma unroll
        for (int nt = 0; nt < 4; nt++) {
            const int c = col0 + wn * 32 + nt * 8 + 2 * tig;
            #pragma unroll
            for (int half = 0; half < 2; half++) {
                const int r = row0 + wm * 64 + mt * 16 + gid + half * 8;
                if (r >= M) continue;
                float v0 = acc[mt][nt][half * 2 + 0];
                float v1 = acc[mt][nt][half * 2 + 1];
                if (CMODE == 2) {
                    if (c < N_real) {
                        v0 += __ldg(&bias[c]);
                        if (RELU) v0 = fmaxf(v0, 0.f);
                        c_ext[(size_t)r * N_real + c] = v0;
                    }
                    if (c + 1 < N_real) {
                        v1 += __ldg(&bias[c + 1]);
                        if (RELU) v1 = fmaxf(v1, 0.f);
                        c_ext[(size_t)r * N_real + c + 1] = v1;
                    }
                } else {
                    v0 += __ldg(&bias[c]);
                    v1 += __ldg(&bias[c + 1]);
                    if (RELU) { v0 = fmaxf(v0, 0.f); v1 = fmaxf(v1, 0.f); }
                    if (CMODE == 1) {
                        *reinterpret_cast<float2*>(&g_hf[(size_t)r * N_real + c]) =
                            make_float2(v0, v1);
                    } else {
                        unsigned hi, lo;
                        split2(v0, v1, hi, lo);
                        const size_t o = (size_t)r * (N_real >> 1) + (c >> 1);
                        C0[o] = hi;
                        C1[o] = lo;
                    }
                }
            }
        }
    }
}

// =============================== launch =====================================
extern "C" void kernel_launch(void* const* d_in, const int* in_sizes, int n_in,
                              void* d_out, int out_size)
{
    const float* x  = (const float*)d_in[0];
    const unsigned int* ei = (const unsigned int*)d_in[1];
    const float* W1 = (const float*)d_in[2];
    const float* b1 = (const float*)d_in[3];
    const float* W2 = (const float*)d_in[4];
    const float* b2 = (const float*)d_in[5];
    const float* W3 = (const float*)d_in[6];
    const float* b3 = (const float*)d_in[7];
    const float* W4 = (const float*)d_in[8];
    const float* b4 = (const float*)d_in[9];
    const float* Wl = (const float*)d_in[10];
    const float* bl = (const float*)d_in[11];
    float* out = (float*)d_out;

    const int M = in_sizes[0] / 128;   // 50000
    const int E = in_sizes[1] / 2;     // 800000
    const dim3 blk(256);
    const int nB   = (M + 255) / 256;
    const int eB   = (E + 255) / 256;
    const int aggB = (M * 32 + 255) / 256;
    const int mT   = (M + 127) / 128;

    const int SMB = 2 * 9472 * 4;      // 75776 B (two stages)
    cudaFuncSetAttribute(gemm_bf16<true , 0>, cudaFuncAttributeMaxDynamicSharedMemorySize, SMB);
    cudaFuncSetAttribute(gemm_bf16<true , 1>, cudaFuncAttributeMaxDynamicSharedMemorySize, SMB);
    cudaFuncSetAttribute(gemm_bf16<false, 2>, cudaFuncAttributeMaxDynamicSharedMemorySize, SMB);

    auto pgrid = [&](int k, int nw) { return ((k >> 1) * nw + 255) / 256; };

    // ---- edge index normalize + CSR build (shared by both layers) ----
    detect_idx64 <<<1,  32 >>>(ei);
    convert_idx  <<<eB, blk>>>(ei, E, M);
    zero_deg     <<<nB, blk>>>(M);
    hist_deg     <<<eB, blk>>>(E);
    scan_block   <<<nB, blk>>>(M);
    scan_partials<<<1,  blk>>>(nB);
    scan_add     <<<nB, blk>>>(M, E);
    fill_csr     <<<eB, blk>>>(E);

    // ---- layer 1 (128 -> 128 -> 128) ----
    gin_aggregate_split<<<aggB, blk>>>(x, 1, M);                         // x -> P
    prep_w<<<pgrid(128, 128), blk>>>(W1, 128, 128, 128);
    gemm_bf16<true , 0><<<dim3(1, mT), blk, SMB>>>(0, 1, nullptr, b1, M, 128, 128, 128); // P -> Q
    prep_w<<<pgrid(128, 128), blk>>>(W2, 128, 128, 128);
    gemm_bf16<true , 1><<<dim3(1, mT), blk, SMB>>>(1, 0, nullptr, b2, M, 128, 128, 128); // Q -> g_hf

    // ---- layer 2 (128 -> 256 -> 256) ----
    gin_aggregate_split<<<aggB, blk>>>(nullptr, 0, M);                   // g_hf -> P
    prep_w<<<pgrid(128, 256), blk>>>(W3, 128, 256, 256);
    gemm_bf16<true , 0><<<dim3(2, mT), blk, SMB>>>(0, 1, nullptr, b3, M, 256, 256, 128); // P -> Q
    prep_w<<<pgrid(256, 256), blk>>>(W4, 256, 256, 256);
    gemm_bf16<true , 0><<<dim3(2, mT), blk, SMB>>>(1, 0, nullptr, b4, M, 256, 256, 256); // Q -> P

    // ---- head (256 -> 40, masked in one 128-wide tile) ----
    prep_w<<<pgrid(256, 128), blk>>>(Wl, 256, 40, 128);
    gemm_bf16<false, 2><<<dim3(1, mT), blk, SMB>>>(0, 0, out, bl, M, 40, 128, 256);      // P -> out
}

// round 13
// speedup vs baseline: 1.1184x; 1.1184x over previous
#include <cuda_runtime.h>
#include <cuda_bf16.h>
#include <cstdint>

// ---------------------------------------------------------------------------
// GIN via mma.sync.m16n8k16.bf16 double-bf16 split (3-product ~fp32):
//   a = a0 + a1 (bf16 each);  D += a0b0 + a0b1 + a1b0  (err ~2^-17/product)
// GEMM: cp.async.cg double-buffered staging, 2 CTAs/SM, 8 warps (2m x 4n),
// warp tile 64x32, BK=32, scalar-LDS fragment loads (ldmatrix regressed).
// All five weight splits fused into ONE prep_all kernel (offset table).
// ---------------------------------------------------------------------------

#define MAXN 50000
#define MAXE 1000000

__device__ __align__(16) unsigned g_P0[MAXN * 128];
__device__ __align__(16) unsigned g_P1[MAXN * 128];
__device__ __align__(16) unsigned g_Q0[MAXN * 128];
__device__ __align__(16) unsigned g_Q1[MAXN * 128];
__device__ __align__(16) float    g_hf[MAXN * 128];   // fp32 h1 (gather2 input)
__device__ __align__(16) unsigned g_W0[81920];        // all split weights, plane 0
__device__ __align__(16) unsigned g_W1[81920];        // plane 1
__device__ int g_rowptr[MAXN + 1];
__device__ int g_cursor[MAXN];
__device__ int g_deg   [MAXN];
__device__ int g_srcs  [MAXE];
__device__ int g_src32 [MAXE];
__device__ int g_dst32 [MAXE];
__device__ int g_bsum  [256];
__device__ int g_is64;

// weight segment offsets (u32 elements within g_W0/g_W1)
#define OFF_W1 0
#define OFF_W2 8192
#define OFF_W3 16384
#define OFF_W4 32768
#define OFF_WL 65536

__device__ __forceinline__ const unsigned* planeR(int sel, int p) {
    if (sel == 0) return p ? g_P1 : g_P0;
    return p ? g_Q1 : g_Q0;
}
__device__ __forceinline__ unsigned* planeW(int sel, int p) {
    if (sel == 0) return p ? g_P1 : g_P0;
    return p ? g_Q1 : g_Q0;
}

__device__ __forceinline__ void split2(float e, float o,
                                       unsigned& hi, unsigned& lo) {
    __nv_bfloat16 he = __float2bfloat16_rn(e);
    __nv_bfloat16 ho = __float2bfloat16_rn(o);
    float re = e - __bfloat162float(he);
    float ro = o - __bfloat162float(ho);
    __nv_bfloat16 rhe = __float2bfloat16_rn(re);
    __nv_bfloat16 rho = __float2bfloat16_rn(ro);
    hi = ((unsigned)__bfloat16_as_ushort(ho) << 16) | __bfloat16_as_ushort(he);
    lo = ((unsigned)__bfloat16_as_ushort(rho) << 16) | __bfloat16_as_ushort(rhe);
}

#define MMA_BF16(d, a, b)                                                     \
    asm volatile(                                                             \
        "mma.sync.aligned.m16n8k16.row.col.f32.bf16.bf16.f32 "               \
        "{%0,%1,%2,%3},{%4,%5,%6,%7},{%8,%9},{%0,%1,%2,%3};"                 \
        : "+f"((d)[0]), "+f"((d)[1]), "+f"((d)[2]), "+f"((d)[3])             \
        : "r"((a)[0]), "r"((a)[1]), "r"((a)[2]), "r"((a)[3]),                \
          "r"((b)[0]), "r"((b)[1]))

// 16B cp.async with zero-fill when pred is false (src-size=0 form)
__device__ __forceinline__ void cp16(uint32_t dst, const void* src, bool pred) {
    int sz = pred ? 16 : 0;
    asm volatile("cp.async.cg.shared.global [%0], [%1], 16, %2;"
                 :: "r"(dst), "l"(src), "r"(sz) : "memory");
}
#define CP_COMMIT() asm volatile("cp.async.commit_group;" ::: "memory")
#define CP_WAIT(n)  asm volatile("cp.async.wait_group %0;" :: "n"(n) : "memory")

// ======================= edge-index dtype handling ==========================
__global__ void detect_idx64(const unsigned int* __restrict__ w) {
    if (threadIdx.x == 0 && blockIdx.x == 0) {
        unsigned int o = 0;
        #pragma unroll 1
        for (int i = 1; i < 256; i += 2) o |= w[i];
        g_is64 = (o == 0) ? 1 : 0;
    }
}
__global__ void convert_idx(const unsigned int* __restrict__ w, int E, int N) {
    const int e = blockIdx.x * blockDim.x + threadIdx.x;
    if (e >= E) return;
    int s, d;
    if (g_is64) { s = (int)w[2 * e]; d = (int)w[2 * (E + e)]; }
    else        { s = (int)w[e];     d = (int)w[E + e]; }
    s = min(max(s, 0), N - 1);
    d = min(max(d, 0), N - 1);
    g_src32[e] = s;
    g_dst32[e] = d;
}

// ============================ CSR construction ==============================
__global__ void zero_deg(int N) {
    int i = blockIdx.x * blockDim.x + threadIdx.x;
    if (i < N) g_deg[i] = 0;
}
__global__ void hist_deg(int E) {
    int e = blockIdx.x * blockDim.x + threadIdx.x;
    if (e < E) atomicAdd(&g_deg[g_dst32[e]], 1);
}
__global__ void scan_block(int N) {
    __shared__ int s[256];
    const int t = threadIdx.x;
    const int i = blockIdx.x * 256 + t;
    const int v = (i < N) ? g_deg[i] : 0;
    s[t] = v;
    __syncthreads();
    #pragma unroll
    for (int off = 1; off < 256; off <<= 1) {
        int tmp = (t >= off) ? s[t - off] : 0;
        __syncthreads();
        s[t] += tmp;
        __syncthreads();
    }
    if (i < N) g_rowptr[i] = s[t] - v;
    if (t == 255) g_bsum[blockIdx.x] = s[255];
}
__global__ void scan_partials(int B) {
    __shared__ int s[256];
    const int t = threadIdx.x;
    const int v = (t < B) ? g_bsum[t] : 0;
    s[t] = v;
    __syncthreads();
    #pragma unroll
    for (int off = 1; off < 256; off <<= 1) {
        int tmp = (t >= off) ? s[t - off] : 0;
        __syncthreads();
        s[t] += tmp;
        __syncthreads();
    }
    if (t < B) g_bsum[t] = s[t] - v;
}
__global__ void scan_add(int N, int E) {
    int i = blockIdx.x * blockDim.x + threadIdx.x;
    if (i < N) {
        int r = g_rowptr[i] + g_bsum[blockIdx.x];
        g_rowptr[i] = r;
        g_cursor[i] = r;
    }
    if (i == N) g_rowptr[N] = E;
}
__global__ void fill_csr(int E) {
    int e = blockIdx.x * blockDim.x + threadIdx.x;
    if (e >= E) return;
    int p = atomicAdd(&g_cursor[g_dst32[e]], 1);
    g_srcs[p] = g_src32[e];
}

// ===================== GIN aggregation (split output) =======================
__global__ void gin_aggregate_split(const float* __restrict__ h_ext,
                                    int use_ext, int N) {
    const int warp = (blockIdx.x * blockDim.x + threadIdx.x) >> 5;
    if (warp >= N) return;
    const int lane = threadIdx.x & 31;
    const float* __restrict__ h = use_ext ? h_ext : g_hf;
    const float4* __restrict__ hp = reinterpret_cast<const float4*>(h);
    float4 acc = hp[(size_t)warp * 32 + lane];
    const int beg = g_rowptr[warp];
    const int end = g_rowptr[warp + 1];
    for (int j = beg; j < end; j++) {
        const int s = g_srcs[j];
        const float4 v = hp[(size_t)s * 32 + lane];
        acc.x += v.x; acc.y += v.y; acc.z += v.z; acc.w += v.w;
    }
    unsigned h0, l0, h1, l1;
    split2(acc.x, acc.y, h0, l0);
    split2(acc.z, acc.w, h1, l1);
    const size_t o = (size_t)warp * 32 + lane;
    reinterpret_cast<uint2*>(g_P0)[o] = make_uint2(h0, h1);
    reinterpret_cast<uint2*>(g_P1)[o] = make_uint2(l0, l1);
}

// =========== fused weight split/pack for ALL five GEMMs =====================
// segment: {w_off, Kh, NW, N_real, src W}
__global__ void prep_all(const float* __restrict__ W1, const float* __restrict__ W2,
                         const float* __restrict__ W3, const float* __restrict__ W4,
                         const float* __restrict__ Wl) {
    int idx = blockIdx.x * blockDim.x + threadIdx.x;
    if (idx >= 81920) return;
    const float* W; int off, NW, N_real;
    if      (idx < OFF_W2) { W = W1; off = OFF_W1; NW = 128; N_real = 128; }
    else if (idx < OFF_W3) { W = W2; off = OFF_W2; NW = 128; N_real = 128; }
    else if (idx < OFF_W4) { W = W3; off = OFF_W3; NW = 256; N_real = 256; }
    else if (idx < OFF_WL) { W = W4; off = OFF_W4; NW = 256; N_real = 256; }
    else                   { W = Wl; off = OFF_WL; NW = 128; N_real = 40;  }
    int rel = idx - off;
    int kp = rel / NW, n = rel % NW;
    float e = 0.f, o = 0.f;
    if (n < N_real) {
        e = W[(size_t)(2 * kp) * N_real + n];
        o = W[(size_t)(2 * kp + 1) * N_real + n];
    }
    unsigned hi, lo;
    split2(e, o, hi, lo);
    g_W0[idx] = hi;
    g_W1[idx] = lo;
}

// ======================= bf16x3 GEMM (mma.m16n8k16) =========================
// cp.async double-buffered. Per stage (u32): As0[128][20] As1 Bs0[16][136] Bs1
// Stage stride = 9472 u32; two stages = 75776 B. Scalar-LDS fragment loads.
// CMODE: 0 = split planes (c_sel), 1 = fp32 g_hf, 2 = external fp32 (masked).
template<bool RELU, int CMODE>
__global__ void __launch_bounds__(256, 2)
gemm_bf16(int a_sel, int c_sel, float* __restrict__ c_ext,
          const float* __restrict__ bias, int w_off,
          int M, int N_real, int NW, int K)
{
    extern __shared__ __align__(16) unsigned smem[];
    constexpr int STG = 9472;            // u32 per stage
    const uint32_t smem_b = (uint32_t)__cvta_generic_to_shared(smem);

    const int tid  = threadIdx.x;
    const int wid  = tid >> 5;
    const int lane = tid & 31;
    const int gid  = lane >> 2;
    const int tig  = lane & 3;
    const int wm   = wid >> 2;
    const int wn   = wid & 3;
    const int row0 = blockIdx.y * 128;
    const int col0 = blockIdx.x * 128;

    const unsigned* __restrict__ A0g = planeR(a_sel, 0);
    const unsigned* __restrict__ A1g = planeR(a_sel, 1);
    const unsigned* __restrict__ W0g = g_W0 + w_off;
    const unsigned* __restrict__ W1g = g_W1 + w_off;

    const int a_r = tid >> 1, a_seg = (tid & 1) * 8;
    const int b_kp = tid >> 4, b_c0 = (tid & 15) * 8;
    const int a_gr = row0 + a_r;
    const bool a_ok = (a_gr < M);
    const int Kh = K >> 1;

    float acc[4][4][4];
    #pragma unroll
    for (int mt = 0; mt < 4; mt++)
        #pragma unroll
        for (int nt = 0; nt < 4; nt++)
            #pragma unroll
            for (int q = 0; q < 4; q++) acc[mt][nt][q] = 0.f;

    auto stage = [&](int ch, int buf) {
        const int kp0 = ch << 4;
        const uint32_t sb = smem_b + (uint32_t)(buf * STG) * 4u;
        const uint32_t a_off = (uint32_t)(a_r * 20 + a_seg) * 4u;
        cp16(sb + a_off,      A0g + (size_t)a_gr * Kh + kp0 + a_seg,     a_ok);
        cp16(sb + a_off + 16, A0g + (size_t)a_gr * Kh + kp0 + a_seg + 4, a_ok);
        cp16(sb + 2560u * 4u + a_off,      A1g + (size_t)a_gr * Kh + kp0 + a_seg,     a_ok);
        cp16(sb + 2560u * 4u + a_off + 16, A1g + (size_t)a_gr * Kh + kp0 + a_seg + 4, a_ok);
        const uint32_t b_off = (uint32_t)(b_kp * 136 + b_c0) * 4u;
        const size_t bg = (size_t)(kp0 + b_kp) * NW + col0 + b_c0;
        cp16(sb + 5120u * 4u + b_off,      W0g + bg,     true);
        cp16(sb + 5120u * 4u + b_off + 16, W0g + bg + 4, true);
        cp16(sb + 7296u * 4u + b_off,      W1g + bg,     true);
        cp16(sb + 7296u * 4u + b_off + 16, W1g + bg + 4, true);
        CP_COMMIT();
    };

    const int nch = K >> 5;
    stage(0, 0);
    for (int ch = 0; ch < nch; ch++) {
        if (ch + 1 < nch) {
            stage(ch + 1, (ch + 1) & 1);
            CP_WAIT(1);
        } else {
            CP_WAIT(0);
        }
        __syncthreads();

        const unsigned* S   = smem + (ch & 1) * STG;
        const unsigned* As0 = S;
        const unsigned* As1 = S + 2560;
        const unsigned* Bs0 = S + 5120;
        const unsigned* Bs1 = S + 7296;

        #pragma unroll
        for (int s = 0; s < 2; s++) {
            const int so = s * 8;
            uint32_t B0f[4][2], B1f[4][2];
            #pragma unroll
            for (int nt = 0; nt < 4; nt++) {
                const int c = wn * 32 + nt * 8 + gid;
                B0f[nt][0] = Bs0[(so + tig    ) * 136 + c];
                B0f[nt][1] = Bs0[(so + tig + 4) * 136 + c];
                B1f[nt][0] = Bs1[(so + tig    ) * 136 + c];
                B1f[nt][1] = Bs1[(so + tig + 4) * 136 + c];
            }
            #pragma unroll
            for (int mt = 0; mt < 4; mt++) {
                const int r = wm * 64 + mt * 16 + gid;
                uint32_t A0f[4], A1f[4];
                A0f[0] = As0[(r    ) * 20 + so + tig    ];
                A0f[1] = As0[(r + 8) * 20 + so + tig    ];
                A0f[2] = As0[(r    ) * 20 + so + tig + 4];
                A0f[3] = As0[(r + 8) * 20 + so + tig + 4];
                A1f[0] = As1[(r    ) * 20 + so + tig    ];
                A1f[1] = As1[(r + 8) * 20 + so + tig    ];
                A1f[2] = As1[(r    ) * 20 + so + tig + 4];
                A1f[3] = As1[(r + 8) * 20 + so + tig + 4];
                #pragma unroll
                for (int nt = 0; nt < 4; nt++)
                    MMA_BF16(acc[mt][nt], A0f, B0f[nt]);   // a0*b0
                #pragma unroll
                for (int nt = 0; nt < 4; nt++)
                    MMA_BF16(acc[mt][nt], A0f, B1f[nt]);   // a0*b1
                #pragma unroll
                for (int nt = 0; nt < 4; nt++)
                    MMA_BF16(acc[mt][nt], A1f, B0f[nt]);   // a1*b0
            }
        }
        __syncthreads();
    }

    // ---- epilogue ----
    unsigned* C0 = planeW(c_sel, 0);
    unsigned* C1 = planeW(c_sel, 1);
    #pragma unroll
    for (int mt = 0; mt < 4; mt++) {
        #pragma unroll
        for (int nt = 0; nt < 4; nt++) {
            const int c = col0 + wn * 32 + nt * 8 + 2 * tig;
            #pragma unroll
            for (int half = 0; half < 2; half++) {
                const int r = row0 + wm * 64 + mt * 16 + gid + half * 8;
                if (r >= M) continue;
                float v0 = acc[mt][nt][half * 2 + 0];
                float v1 = acc[mt][nt][half * 2 + 1];
                if (CMODE == 2) {
                    if (c < N_real) {
                        v0 += __ldg(&bias[c]);
                        if (RELU) v0 = fmaxf(v0, 0.f);
                        c_ext[(size_t)r * N_real + c] = v0;
                    }
                    if (c + 1 < N_real) {
                        v1 += __ldg(&bias[c + 1]);
                        if (RELU) v1 = fmaxf(v1, 0.f);
                        c_ext[(size_t)r * N_real + c + 1] = v1;
                    }
                } else {
                    v0 += __ldg(&bias[c]);
                    v1 += __ldg(&bias[c + 1]);
                    if (RELU) { v0 = fmaxf(v0, 0.f); v1 = fmaxf(v1, 0.f); }
                    if (CMODE == 1) {
                        *reinterpret_cast<float2*>(&g_hf[(size_t)r * N_real + c]) =
                            make_float2(v0, v1);
                    } else {
                        unsigned hi, lo;
                        split2(v0, v1, hi, lo);
                        const size_t o = (size_t)r * (N_real >> 1) + (c >> 1);
                        C0[o] = hi;
                        C1[o] = lo;
                    }
                }
            }
        }
    }
}

// =============================== launch =====================================
extern "C" void kernel_launch(void* const* d_in, const int* in_sizes, int n_in,
                              void* d_out, int out_size)
{
    const float* x  = (const float*)d_in[0];
    const unsigned int* ei = (const unsigned int*)d_in[1];
    const float* W1 = (const float*)d_in[2];
    const float* b1 = (const float*)d_in[3];
    const float* W2 = (const float*)d_in[4];
    const float* b2 = (const float*)d_in[5];
    const float* W3 = (const float*)d_in[6];
    const float* b3 = (const float*)d_in[7];
    const float* W4 = (const float*)d_in[8];
    const float* b4 = (const float*)d_in[9];
    const float* Wl = (const float*)d_in[10];
    const float* bl = (const float*)d_in[11];
    float* out = (float*)d_out;

    const int M = in_sizes[0] / 128;   // 50000
    const int E = in_sizes[1] / 2;     // 800000
    const dim3 blk(256);
    const int nB   = (M + 255) / 256;
    const int eB   = (E + 255) / 256;
    const int aggB = (M * 32 + 255) / 256;
    const int mT   = (M + 127) / 128;

    const int SMB = 2 * 9472 * 4;      // 75776 B (two stages)
    cudaFuncSetAttribute(gemm_bf16<true , 0>, cudaFuncAttributeMaxDynamicSharedMemorySize, SMB);
    cudaFuncSetAttribute(gemm_bf16<true , 1>, cudaFuncAttributeMaxDynamicSharedMemorySize, SMB);
    cudaFuncSetAttribute(gemm_bf16<false, 2>, cudaFuncAttributeMaxDynamicSharedMemorySize, SMB);

    // ---- weight split (all five, one kernel) + edge/CSR build ----
    prep_all     <<<(81920 + 255) / 256, blk>>>(W1, W2, W3, W4, Wl);
    detect_idx64 <<<1,  32 >>>(ei);
    convert_idx  <<<eB, blk>>>(ei, E, M);
    zero_deg     <<<nB, blk>>>(M);
    hist_deg     <<<eB, blk>>>(E);
    scan_block   <<<nB, blk>>>(M);
    scan_partials<<<1,  blk>>>(nB);
    scan_add     <<<nB, blk>>>(M, E);
    fill_csr     <<<eB, blk>>>(E);

    // ---- layer 1 (128 -> 128 -> 128) ----
    gin_aggregate_split<<<aggB, blk>>>(x, 1, M);                         // x -> P
    gemm_bf16<true , 0><<<dim3(1, mT), blk, SMB>>>(0, 1, nullptr, b1, OFF_W1, M, 128, 128, 128); // P -> Q
    gemm_bf16<true , 1><<<dim3(1, mT), blk, SMB>>>(1, 0, nullptr, b2, OFF_W2, M, 128, 128, 128); // Q -> g_hf

    // ---- layer 2 (128 -> 256 -> 256) ----
    gin_aggregate_split<<<aggB, blk>>>(nullptr, 0, M);                   // g_hf -> P
    gemm_bf16<true , 0><<<dim3(2, mT), blk, SMB>>>(0, 1, nullptr, b3, OFF_W3, M, 256, 256, 128); // P -> Q
    gemm_bf16<true , 0><<<dim3(2, mT), blk, SMB>>>(1, 0, nullptr, b4, OFF_W4, M, 256, 256, 256); // Q -> P

    // ---- head (256 -> 40, masked in one 128-wide tile) ----
    gemm_bf16<false, 2><<<dim3(1, mT), blk, SMB>>>(0, 0, out, bl, OFF_WL, M, 40, 128, 256);      // P -> out
}

// round 14
// speedup vs baseline: 1.2209x; 1.0916x over previous
#include <cuda_runtime.h>
#include <cuda_bf16.h>
#include <cstdint>

// ---------------------------------------------------------------------------
// GIN via mma.sync.m16n8k16.bf16 double-bf16 split (3-product ~fp32):
//   a = a0 + a1 (bf16 each);  D += a0b0 + a0b1 + a1b0  (err ~2^-17/product)
// GEMM: cp.async.cg double-buffered staging, 2 CTAs/SM, 8 warps (2m x 4n),
// warp tile 64x32, BK=32, scalar-LDS fragment loads.
// R14: setup launches fused (prep_all zeroes deg; convert+detect+hist one
// kernel); head GEMM uses a 64-col tile (NTL=2) to skip padded columns.
// ---------------------------------------------------------------------------

#define MAXN 50000
#define MAXE 1000000

__device__ __align__(16) unsigned g_P0[MAXN * 128];
__device__ __align__(16) unsigned g_P1[MAXN * 128];
__device__ __align__(16) unsigned g_Q0[MAXN * 128];
__device__ __align__(16) unsigned g_Q1[MAXN * 128];
__device__ __align__(16) float    g_hf[MAXN * 128];   // fp32 h1 (gather2 input)
__device__ __align__(16) unsigned g_W0[81920];        // all split weights, plane 0
__device__ __align__(16) unsigned g_W1[81920];        // plane 1
__device__ int g_rowptr[MAXN + 1];
__device__ int g_cursor[MAXN];
__device__ int g_deg   [MAXN];
__device__ int g_srcs  [MAXE];
__device__ int g_src32 [MAXE];
__device__ int g_dst32 [MAXE];
__device__ int g_bsum  [256];

// weight segment offsets (u32 elements within g_W0/g_W1)
#define OFF_W1 0
#define OFF_W2 8192
#define OFF_W3 16384
#define OFF_W4 32768
#define OFF_WL 65536

__device__ __forceinline__ const unsigned* planeR(int sel, int p) {
    if (sel == 0) return p ? g_P1 : g_P0;
    return p ? g_Q1 : g_Q0;
}
__device__ __forceinline__ unsigned* planeW(int sel, int p) {
    if (sel == 0) return p ? g_P1 : g_P0;
    return p ? g_Q1 : g_Q0;
}

__device__ __forceinline__ void split2(float e, float o,
                                       unsigned& hi, unsigned& lo) {
    __nv_bfloat16 he = __float2bfloat16_rn(e);
    __nv_bfloat16 ho = __float2bfloat16_rn(o);
    float re = e - __bfloat162float(he);
    float ro = o - __bfloat162float(ho);
    __nv_bfloat16 rhe = __float2bfloat16_rn(re);
    __nv_bfloat16 rho = __float2bfloat16_rn(ro);
    hi = ((unsigned)__bfloat16_as_ushort(ho) << 16) | __bfloat16_as_ushort(he);
    lo = ((unsigned)__bfloat16_as_ushort(rho) << 16) | __bfloat16_as_ushort(rhe);
}

#define MMA_BF16(d, a, b)                                                     \
    asm volatile(                                                             \
        "mma.sync.aligned.m16n8k16.row.col.f32.bf16.bf16.f32 "               \
        "{%0,%1,%2,%3},{%4,%5,%6,%7},{%8,%9},{%0,%1,%2,%3};"                 \
        : "+f"((d)[0]), "+f"((d)[1]), "+f"((d)[2]), "+f"((d)[3])             \
        : "r"((a)[0]), "r"((a)[1]), "r"((a)[2]), "r"((a)[3]),                \
          "r"((b)[0]), "r"((b)[1]))

// 16B cp.async with zero-fill when pred is false (src-size=0 form)
__device__ __forceinline__ void cp16(uint32_t dst, const void* src, bool pred) {
    int sz = pred ? 16 : 0;
    asm volatile("cp.async.cg.shared.global [%0], [%1], 16, %2;"
                 :: "r"(dst), "l"(src), "r"(sz) : "memory");
}
#define CP_COMMIT() asm volatile("cp.async.commit_group;" ::: "memory")
#define CP_WAIT(n)  asm volatile("cp.async.wait_group %0;" :: "n"(n) : "memory")

// =========== fused: weight split/pack for ALL five GEMMs + deg zero =========
__global__ void prep_all(const float* __restrict__ W1, const float* __restrict__ W2,
                         const float* __restrict__ W3, const float* __restrict__ W4,
                         const float* __restrict__ Wl, int N) {
    int idx = blockIdx.x * blockDim.x + threadIdx.x;
    if (idx < N) g_deg[idx] = 0;          // fold zero_deg into this launch
    if (idx >= 81920) return;
    const float* W; int off, NW, N_real;
    if      (idx < OFF_W2) { W = W1; off = OFF_W1; NW = 128; N_real = 128; }
    else if (idx < OFF_W3) { W = W2; off = OFF_W2; NW = 128; N_real = 128; }
    else if (idx < OFF_W4) { W = W3; off = OFF_W3; NW = 256; N_real = 256; }
    else if (idx < OFF_WL) { W = W4; off = OFF_W4; NW = 256; N_real = 256; }
    else                   { W = Wl; off = OFF_WL; NW = 128; N_real = 40;  }
    int rel = idx - off;
    int kp = rel / NW, n = rel % NW;
    float e = 0.f, o = 0.f;
    if (n < N_real) {
        e = W[(size_t)(2 * kp) * N_real + n];
        o = W[(size_t)(2 * kp + 1) * N_real + n];
    }
    unsigned hi, lo;
    split2(e, o, hi, lo);
    g_W0[idx] = hi;
    g_W1[idx] = lo;
}

// =========== fused: dtype detect + index convert + degree histogram =========
// int64 (LE, values < 2^31): odd 32-bit words all zero; int32: OR != 0 w.h.p.
__global__ void convert_hist(const unsigned int* __restrict__ w, int E, int N) {
    __shared__ int s_is64;
    if (threadIdx.x < 32) {
        unsigned int o = 0;
        for (int i = 1 + 2 * (int)threadIdx.x; i < 256; i += 64) o |= w[i];
        #pragma unroll
        for (int k = 16; k > 0; k >>= 1)
            o |= __shfl_down_sync(0xffffffffu, o, k);
        if (threadIdx.x == 0) s_is64 = (o == 0) ? 1 : 0;
    }
    __syncthreads();
    const int is64 = s_is64;
    const int e = blockIdx.x * blockDim.x + threadIdx.x;
    if (e >= E) return;
    int s, d;
    if (is64) { s = (int)w[2 * e]; d = (int)w[2 * (E + e)]; }
    else      { s = (int)w[e];     d = (int)w[E + e]; }
    s = min(max(s, 0), N - 1);
    d = min(max(d, 0), N - 1);
    g_src32[e] = s;
    g_dst32[e] = d;
    atomicAdd(&g_deg[d], 1);
}

// ============================ CSR construction ==============================
__global__ void scan_block(int N) {
    __shared__ int s[256];
    const int t = threadIdx.x;
    const int i = blockIdx.x * 256 + t;
    const int v = (i < N) ? g_deg[i] : 0;
    s[t] = v;
    __syncthreads();
    #pragma unroll
    for (int off = 1; off < 256; off <<= 1) {
        int tmp = (t >= off) ? s[t - off] : 0;
        __syncthreads();
        s[t] += tmp;
        __syncthreads();
    }
    if (i < N) g_rowptr[i] = s[t] - v;
    if (t == 255) g_bsum[blockIdx.x] = s[255];
}
__global__ void scan_partials(int B) {
    __shared__ int s[256];
    const int t = threadIdx.x;
    const int v = (t < B) ? g_bsum[t] : 0;
    s[t] = v;
    __syncthreads();
    #pragma unroll
    for (int off = 1; off < 256; off <<= 1) {
        int tmp = (t >= off) ? s[t - off] : 0;
        __syncthreads();
        s[t] += tmp;
        __syncthreads();
    }
    if (t < B) g_bsum[t] = s[t] - v;
}
__global__ void scan_add(int N, int E) {
    int i = blockIdx.x * blockDim.x + threadIdx.x;
    if (i < N) {
        int r = g_rowptr[i] + g_bsum[blockIdx.x];
        g_rowptr[i] = r;
        g_cursor[i] = r;
    }
    if (i == N) g_rowptr[N] = E;
}
__global__ void fill_csr(int E) {
    int e = blockIdx.x * blockDim.x + threadIdx.x;
    if (e >= E) return;
    int p = atomicAdd(&g_cursor[g_dst32[e]], 1);
    g_srcs[p] = g_src32[e];
}

// ===================== GIN aggregation (split output) =======================
__global__ void gin_aggregate_split(const float* __restrict__ h_ext,
                                    int use_ext, int N) {
    const int warp = (blockIdx.x * blockDim.x + threadIdx.x) >> 5;
    if (warp >= N) return;
    const int lane = threadIdx.x & 31;
    const float* __restrict__ h = use_ext ? h_ext : g_hf;
    const float4* __restrict__ hp = reinterpret_cast<const float4*>(h);
    float4 acc = hp[(size_t)warp * 32 + lane];
    const int beg = g_rowptr[warp];
    const int end = g_rowptr[warp + 1];
    for (int j = beg; j < end; j++) {
        const int s = g_srcs[j];
        const float4 v = hp[(size_t)s * 32 + lane];
        acc.x += v.x; acc.y += v.y; acc.z += v.z; acc.w += v.w;
    }
    unsigned h0, l0, h1, l1;
    split2(acc.x, acc.y, h0, l0);
    split2(acc.z, acc.w, h1, l1);
    const size_t o = (size_t)warp * 32 + lane;
    reinterpret_cast<uint2*>(g_P0)[o] = make_uint2(h0, h1);
    reinterpret_cast<uint2*>(g_P1)[o] = make_uint2(l0, l1);
}

// ======================= bf16x3 GEMM (mma.m16n8k16) =========================
// cp.async double-buffered. Per stage (u32): As0[128][20] As1 Bs0[16][136] Bs1
// Stage stride = 9472 u32; two stages = 75776 B. Scalar-LDS fragment loads.
// NTL = n-subtiles per warp (4 -> 128-col block, 2 -> 64-col block for head).
// Warp n-offset = wn * (NTL*8). CMODE: 0 split planes, 1 fp32 g_hf, 2 ext.
template<bool RELU, int CMODE, int NTL>
__global__ void __launch_bounds__(256, 2)
gemm_bf16(int a_sel, int c_sel, float* __restrict__ c_ext,
          const float* __restrict__ bias, int w_off,
          int M, int N_real, int NW, int K)
{
    extern __shared__ __align__(16) unsigned smem[];
    constexpr int STG = 9472;            // u32 per stage
    constexpr int BCOLS = NTL * 32;      // block column coverage (4 warps-n)
    const uint32_t smem_b = (uint32_t)__cvta_generic_to_shared(smem);

    const int tid  = threadIdx.x;
    const int wid  = tid >> 5;
    const int lane = tid & 31;
    const int gid  = lane >> 2;
    const int tig  = lane & 3;
    const int wm   = wid >> 2;
    const int wn   = wid & 3;
    const int row0 = blockIdx.y * 128;
    const int col0 = blockIdx.x * BCOLS;

    const unsigned* __restrict__ A0g = planeR(a_sel, 0);
    const unsigned* __restrict__ A1g = planeR(a_sel, 1);
    const unsigned* __restrict__ W0g = g_W0 + w_off;
    const unsigned* __restrict__ W1g = g_W1 + w_off;

    const int a_r = tid >> 1, a_seg = (tid & 1) * 8;
    const int b_kp = tid >> 4, b_c0 = (tid & 15) * 8;
    const int a_gr = row0 + a_r;
    const bool a_ok = (a_gr < M);
    const bool b_ok = (b_c0 < BCOLS);    // head: skip cols >= 64 (unread)
    const int Kh = K >> 1;

    float acc[4][NTL][4];
    #pragma unroll
    for (int mt = 0; mt < 4; mt++)
        #pragma unroll
        for (int nt = 0; nt < NTL; nt++)
            #pragma unroll
            for (int q = 0; q < 4; q++) acc[mt][nt][q] = 0.f;

    auto stage = [&](int ch, int buf) {
        const int kp0 = ch << 4;
        const uint32_t sb = smem_b + (uint32_t)(buf * STG) * 4u;
        const uint32_t a_off = (uint32_t)(a_r * 20 + a_seg) * 4u;
        cp16(sb + a_off,      A0g + (size_t)a_gr * Kh + kp0 + a_seg,     a_ok);
        cp16(sb + a_off + 16, A0g + (size_t)a_gr * Kh + kp0 + a_seg + 4, a_ok);
        cp16(sb + 2560u * 4u + a_off,      A1g + (size_t)a_gr * Kh + kp0 + a_seg,     a_ok);
        cp16(sb + 2560u * 4u + a_off + 16, A1g + (size_t)a_gr * Kh + kp0 + a_seg + 4, a_ok);
        const uint32_t b_off = (uint32_t)(b_kp * 136 + b_c0) * 4u;
        const size_t bg = (size_t)(kp0 + b_kp) * NW + col0 + b_c0;
        cp16(sb + 5120u * 4u + b_off,      W0g + bg,     b_ok);
        cp16(sb + 5120u * 4u + b_off + 16, W0g + bg + 4, b_ok);
        cp16(sb + 7296u * 4u + b_off,      W1g + bg,     b_ok);
        cp16(sb + 7296u * 4u + b_off + 16, W1g + bg + 4, b_ok);
        CP_COMMIT();
    };

    const int nch = K >> 5;
    stage(0, 0);
    for (int ch = 0; ch < nch; ch++) {
        if (ch + 1 < nch) {
            stage(ch + 1, (ch + 1) & 1);
            CP_WAIT(1);
        } else {
            CP_WAIT(0);
        }
        __syncthreads();

        const unsigned* S   = smem + (ch & 1) * STG;
        const unsigned* As0 = S;
        const unsigned* As1 = S + 2560;
        const unsigned* Bs0 = S + 5120;
        const unsigned* Bs1 = S + 7296;

        #pragma unroll
        for (int s = 0; s < 2; s++) {
            const int so = s * 8;
            uint32_t B0f[NTL][2], B1f[NTL][2];
            #pragma unroll
            for (int nt = 0; nt < NTL; nt++) {
                const int c = wn * (NTL * 8) + nt * 8 + gid;
                B0f[nt][0] = Bs0[(so + tig    ) * 136 + c];
                B0f[nt][1] = Bs0[(so + tig + 4) * 136 + c];
                B1f[nt][0] = Bs1[(so + tig    ) * 136 + c];
                B1f[nt][1] = Bs1[(so + tig + 4) * 136 + c];
            }
            #pragma unroll
            for (int mt = 0; mt < 4; mt++) {
                const int r = wm * 64 + mt * 16 + gid;
                uint32_t A0f[4], A1f[4];
                A0f[0] = As0[(r    ) * 20 + so + tig    ];
                A0f[1] = As0[(r + 8) * 20 + so + tig    ];
                A0f[2] = As0[(r    ) * 20 + so + tig + 4];
                A0f[3] = As0[(r + 8) * 20 + so + tig + 4];
                A1f[0] = As1[(r    ) * 20 + so + tig    ];
                A1f[1] = As1[(r + 8) * 20 + so + tig    ];
                A1f[2] = As1[(r    ) * 20 + so + tig + 4];
                A1f[3] = As1[(r + 8) * 20 + so + tig + 4];
                #pragma unroll
                for (int nt = 0; nt < NTL; nt++)
                    MMA_BF16(acc[mt][nt], A0f, B0f[nt]);   // a0*b0
                #pragma unroll
                for (int nt = 0; nt < NTL; nt++)
                    MMA_BF16(acc[mt][nt], A0f, B1f[nt]);   // a0*b1
                #pragma unroll
                for (int nt = 0; nt < NTL; nt++)
                    MMA_BF16(acc[mt][nt], A1f, B0f[nt]);   // a1*b0
            }
        }
        __syncthreads();
    }

    // ---- epilogue ----
    unsigned* C0 = planeW(c_sel, 0);
    unsigned* C1 = planeW(c_sel, 1);
    #pragma unroll
    for (int mt = 0; mt < 4; mt++) {
        #pragma unroll
        for (int nt = 0; nt < NTL; nt++) {
            const int c = col0 + wn * (NTL * 8) + nt * 8 + 2 * tig;
            #pragma unroll
            for (int half = 0; half < 2; half++) {
                const int r = row0 + wm * 64 + mt * 16 + gid + half * 8;
                if (r >= M) continue;
                float v0 = acc[mt][nt][half * 2 + 0];
                float v1 = acc[mt][nt][half * 2 + 1];
                if (CMODE == 2) {
                    if (c < N_real) {
                        v0 += __ldg(&bias[c]);
                        if (RELU) v0 = fmaxf(v0, 0.f);
                        c_ext[(size_t)r * N_real + c] = v0;
                    }
                    if (c + 1 < N_real) {
                        v1 += __ldg(&bias[c + 1]);
                        if (RELU) v1 = fmaxf(v1, 0.f);
                        c_ext[(size_t)r * N_real + c + 1] = v1;
                    }
                } else {
                    v0 += __ldg(&bias[c]);
                    v1 += __ldg(&bias[c + 1]);
                    if (RELU) { v0 = fmaxf(v0, 0.f); v1 = fmaxf(v1, 0.f); }
                    if (CMODE == 1) {
                        *reinterpret_cast<float2*>(&g_hf[(size_t)r * N_real + c]) =
                            make_float2(v0, v1);
                    } else {
                        unsigned hi, lo;
                        split2(v0, v1, hi, lo);
                        const size_t o = (size_t)r * (N_real >> 1) + (c >> 1);
                        C0[o] = hi;
                        C1[o] = lo;
                    }
                }
            }
        }
    }
}

// =============================== launch =====================================
extern "C" void kernel_launch(void* const* d_in, const int* in_sizes, int n_in,
                              void* d_out, int out_size)
{
    const float* x  = (const float*)d_in[0];
    const unsigned int* ei = (const unsigned int*)d_in[1];
    const float* W1 = (const float*)d_in[2];
    const float* b1 = (const float*)d_in[3];
    const float* W2 = (const float*)d_in[4];
    const float* b2 = (const float*)d_in[5];
    const float* W3 = (const float*)d_in[6];
    const float* b3 = (const float*)d_in[7];
    const float* W4 = (const float*)d_in[8];
    const float* b4 = (const float*)d_in[9];
    const float* Wl = (const float*)d_in[10];
    const float* bl = (const float*)d_in[11];
    float* out = (float*)d_out;

    const int M = in_sizes[0] / 128;   // 50000
    const int E = in_sizes[1] / 2;     // 800000
    const dim3 blk(256);
    const int nB   = (M + 255) / 256;
    const int eB   = (E + 255) / 256;
    const int aggB = (M * 32 + 255) / 256;
    const int mT   = (M + 127) / 128;

    const int SMB = 2 * 9472 * 4;      // 75776 B (two stages)
    cudaFuncSetAttribute(gemm_bf16<true , 0, 4>, cudaFuncAttributeMaxDynamicSharedMemorySize, SMB);
    cudaFuncSetAttribute(gemm_bf16<true , 1, 4>, cudaFuncAttributeMaxDynamicSharedMemorySize, SMB);
    cudaFuncSetAttribute(gemm_bf16<false, 2, 2>, cudaFuncAttributeMaxDynamicSharedMemorySize, SMB);

    // ---- fused setup: weight split + deg zero; convert+detect+hist ----
    prep_all    <<<(81920 + 255) / 256, blk>>>(W1, W2, W3, W4, Wl, M);
    convert_hist<<<eB, blk>>>(ei, E, M);
    scan_block   <<<nB, blk>>>(M);
    scan_partials<<<1,  blk>>>(nB);
    scan_add     <<<nB, blk>>>(M, E);
    fill_csr     <<<eB, blk>>>(E);

    // ---- layer 1 (128 -> 128 -> 128) ----
    gin_aggregate_split<<<aggB, blk>>>(x, 1, M);                         // x -> P
    gemm_bf16<true , 0, 4><<<dim3(1, mT), blk, SMB>>>(0, 1, nullptr, b1, OFF_W1, M, 128, 128, 128); // P -> Q
    gemm_bf16<true , 1, 4><<<dim3(1, mT), blk, SMB>>>(1, 0, nullptr, b2, OFF_W2, M, 128, 128, 128); // Q -> g_hf

    // ---- layer 2 (128 -> 256 -> 256) ----
    gin_aggregate_split<<<aggB, blk>>>(nullptr, 0, M);                   // g_hf -> P
    gemm_bf16<true , 0, 4><<<dim3(2, mT), blk, SMB>>>(0, 1, nullptr, b3, OFF_W3, M, 256, 256, 128); // P -> Q
    gemm_bf16<true , 0, 4><<<dim3(2, mT), blk, SMB>>>(1, 0, nullptr, b4, OFF_W4, M, 256, 256, 256); // Q -> P

    // ---- head (256 -> 40, 64-col tile NTL=2) ----
    gemm_bf16<false, 2, 2><<<dim3(1, mT), blk, SMB>>>(0, 0, out, bl, OFF_WL, M, 40, 128, 256);      // P -> out
}